// round 7
// baseline (speedup 1.0000x reference)
#include <cuda_runtime.h>
#include <math.h>

// Problem constants
namespace {
constexpr int Gd = 4, Td = 4096, Dd = 2048, Ed = 64, Cd = 128;
constexpr int GT = Gd * Td;                         // 16384 tokens
constexpr long long GTEC = (long long)GT * Ed * Cd; // 134217728
constexpr int NB_G = 256;                           // GEMM blocks (64 rows each)
}

// Scratch (fully overwritten every launch -> deterministic)
__device__ float g_gate1[GT];
__device__ float g_gate2[GT];
__device__ int   g_idx[GT];                // idx1 | idx2<<8
__device__ float g_sumP_part[NB_G][Ed];    // per-block sum of probs per expert
__device__ float g_z_part[NB_G];           // per-block z-loss partial
__device__ int   g_cnt[Gd * Ed];           // tokens per (group, expert) in top-2

// ---------------------------------------------------------------------------
// Kernel 1: router GEMM (64 rows x 64 experts per block, K=2048) + softmax
// + top-2 + loss partials. Zero-fill is handled by a cudaMemsetAsync node.
// ---------------------------------------------------------------------------
__global__ void __launch_bounds__(256, 4) k_gemm(const float* __restrict__ X,
                                                  const float* __restrict__ W,
                                                  const float* __restrict__ bias_v) {
    const int tid = threadIdx.x;
    const int bid = blockIdx.x;

    __shared__ float smem_raw[64 * 65];     // 16.6KB: As+Bs_dup union tileS
    __shared__ float rowz[64];
    float (*As)[64]   = (float(*)[64])smem_raw;            // [16][64]   4KB
    float (*Bsd)[128] = (float(*)[128])(smem_raw + 1024);  // [16][128]  8KB (dup pairs)
    float (*S)[65]    = (float(*)[65])smem_raw;            // [64][65] (after loop)

    const int m0 = bid * 64;
    const int tx = tid & 15;   // 16 in N dir -> 4 cols each
    const int ty = tid >> 4;   // 16 in M dir -> 4 rows each (2 row-pairs)

    unsigned long long acc2[2][4];
#pragma unroll
    for (int i = 0; i < 2; i++)
#pragma unroll
        for (int j = 0; j < 4; j++) acc2[i][j] = 0ull;

    const int rA = tid >> 2, qA = tid & 3;          // X tile: 256 float4s
    const int kkW = tid >> 4, e4W = tid & 15;       // W tile: 256 float4s
    const float* Xp = X + (long long)(m0 + rA) * Dd + qA * 4;
    const float* Wp = W + (long long)kkW * Ed + e4W * 4;

    float4 xa = *(const float4*)Xp;
    float4 wb = *(const float4*)Wp;
    As[qA * 4 + 0][rA] = xa.x; As[qA * 4 + 1][rA] = xa.y;
    As[qA * 4 + 2][rA] = xa.z; As[qA * 4 + 3][rA] = xa.w;
    {   // store B duplicated: cols e4W*4..+3 -> pairs at [e4W*8 .. +7]
        float4 d0 = make_float4(wb.x, wb.x, wb.y, wb.y);
        float4 d1 = make_float4(wb.z, wb.z, wb.w, wb.w);
        *(float4*)&Bsd[kkW][e4W * 8]     = d0;
        *(float4*)&Bsd[kkW][e4W * 8 + 4] = d1;
    }
    __syncthreads();

    constexpr int NTILES = Dd / 16;   // 128
    for (int t = 0; t < NTILES; t++) {
        if (t + 1 < NTILES) {
            xa = *(const float4*)(Xp + (t + 1) * 16);
            wb = *(const float4*)(Wp + (long long)(t + 1) * 16 * Ed);
        }
#pragma unroll
        for (int kk = 0; kk < 16; kk++) {
            ulonglong2 aA = *(const ulonglong2*)&As[kk][ty * 4];
            unsigned long long ap[2] = {aA.x, aA.y};
            ulonglong2 b0 = *(const ulonglong2*)&Bsd[kk][tx * 8];
            ulonglong2 b1 = *(const ulonglong2*)&Bsd[kk][tx * 8 + 4];
            unsigned long long bd[4] = {b0.x, b0.y, b1.x, b1.y};
#pragma unroll
            for (int i = 0; i < 2; i++)
#pragma unroll
                for (int j = 0; j < 4; j++)
                    asm("fma.rn.f32x2 %0, %1, %2, %0;"
                        : "+l"(acc2[i][j]) : "l"(ap[i]), "l"(bd[j]));
        }
        __syncthreads();
        if (t + 1 < NTILES) {
            As[qA * 4 + 0][rA] = xa.x; As[qA * 4 + 1][rA] = xa.y;
            As[qA * 4 + 2][rA] = xa.z; As[qA * 4 + 3][rA] = xa.w;
            float4 d0 = make_float4(wb.x, wb.x, wb.y, wb.y);
            float4 d1 = make_float4(wb.z, wb.z, wb.w, wb.w);
            *(float4*)&Bsd[kkW][e4W * 8]     = d0;
            *(float4*)&Bsd[kkW][e4W * 8 + 4] = d1;
            __syncthreads();
        }
    }

    // unpack accumulators (+bias) into S as logits (As/Bsd dead now)
    float bcol[4];
    *(float4*)bcol = *(const float4*)&bias_v[tx * 4];
#pragma unroll
    for (int i = 0; i < 2; i++) {
#pragma unroll
        for (int j = 0; j < 4; j++) {
            float lo, hi;
            asm("mov.b64 {%0,%1}, %2;" : "=f"(lo), "=f"(hi) : "l"(acc2[i][j]));
            S[ty * 4 + 2 * i + 0][tx * 4 + j] = lo + bcol[j];
            S[ty * 4 + 2 * i + 1][tx * 4 + j] = hi + bcol[j];
        }
    }
    __syncthreads();

    // per-row softmax / top-2 / z partial (64 rows, one thread per row)
    if (tid < 64) {
        const int r = tid;
        const int row = m0 + r;
        float mx = -3.0e38f;
#pragma unroll 8
        for (int e = 0; e < Ed; e++) mx = fmaxf(mx, S[r][e]);
        float sum = 0.f;
        float l1 = -3.0e38f, l2 = -3.0e38f;
        int i1 = 0, i2 = 0;
        for (int e = 0; e < Ed; e++) {
            float L = S[r][e];
            sum += expf(L - mx);
            if (L > l1) { l2 = l1; i2 = i1; l1 = L; i1 = e; }
            else if (L > l2) { l2 = L; i2 = e; }
        }
        float lse = mx + logf(sum);
        float zr = 0.f;
        for (int e = 0; e < Ed; e++) {
            float d = S[r][e] - lse;
            zr += d * d;
        }
        rowz[r] = zr;
        g_gate1[row] = expf(l1 - mx) / sum;
        g_gate2[row] = expf(l2 - mx) / sum;
        g_idx[row] = i1 | (i2 << 8);
        for (int e = 0; e < Ed; e++) S[r][e] = expf(S[r][e] - mx) / sum;
    }
    __syncthreads();

    // column sums of probs -> per-block partials for aux loss
    if (tid < 64) {
        float s = 0.f;
#pragma unroll 8
        for (int r = 0; r < 64; r++) s += S[r][tid];
        g_sumP_part[bid][tid] = s;
    }
    if (tid < 32) {
        float s = rowz[tid] + rowz[tid + 32];
#pragma unroll
        for (int o = 16; o; o >>= 1) s += __shfl_xor_sync(0xffffffffu, s, o);
        if (tid == 0) g_z_part[bid] = s;
    }
}

// ---------------------------------------------------------------------------
// Kernel 2: per-group BPR sort + capacity assignment + sparse scatter.
// One block per group, 1024 threads.
// ---------------------------------------------------------------------------
__global__ void __launch_bounds__(1024) k_route(float* __restrict__ out) {
    __shared__ unsigned long long keys[4096];  // 32KB (later reused as hist)
    __shared__ unsigned short tok[4096];       // 8KB

    const int tid = threadIdx.x;
    const int g = blockIdx.x;
    const int lane = tid & 31;
    const int warp = tid >> 5;                 // 0..31
    const unsigned lt = (1u << lane) - 1u;

    // keys: descending gate1, ties -> ascending token index (stable)
    for (int i = tid; i < Td; i += 1024) {
        unsigned u = __float_as_uint(g_gate1[g * Td + i]);
        unsigned o = (u >> 31) ? ~u : (u | 0x80000000u);
        keys[i] = (((unsigned long long)(~o)) << 32) | (unsigned)i;
    }
    __syncthreads();

    // bitonic sort ascending (4096 elements)
    for (unsigned k = 2; k <= 4096; k <<= 1) {
        for (unsigned j = k >> 1; j > 0; j >>= 1) {
            for (unsigned i = tid; i < 4096; i += 1024) {
                unsigned ixj = i ^ j;
                if (ixj > i) {
                    unsigned long long a = keys[i], b = keys[ixj];
                    bool up = ((i & k) == 0);
                    if ((a > b) == up) { keys[i] = b; keys[ixj] = a; }
                }
            }
            __syncthreads();
        }
    }

    for (int i = tid; i < Td; i += 1024) tok[i] = (unsigned short)(keys[i] & 0xffffu);
    __syncthreads();

    unsigned short* hist = (unsigned short*)keys;  // [128 chunks][64 experts]
    unsigned* h32 = (unsigned*)keys;

    int tot1 = 0;  // per-expert top-1 totals kept in registers of threads tid<64

    for (int s = 0; s < 2; s++) {
        for (int i = tid; i < 4096; i += 1024) h32[i] = 0u;
        __syncthreads();

        int myE[4], myLr[4], myT[4];
#pragma unroll
        for (int jj = 0; jj < 4; jj++) {
            int c = warp * 4 + jj;          // chunk of 32 sorted positions
            int p = c * 32 + lane;
            int t = tok[p];
            int packed = g_idx[g * Td + t];
            int e = (s == 0) ? (packed & 0xff) : ((packed >> 8) & 0xff);
            unsigned m = __match_any_sync(0xffffffffu, e);
            int lr = __popc(m & lt);
            if ((m & lt) == 0) hist[c * 64 + e] = (unsigned short)__popc(m);
            myE[jj] = e; myLr[jj] = lr; myT[jj] = t;
        }
        __syncthreads();

        // exclusive scan over chunks per expert
        if (tid < 64) {
            int run = (s == 0) ? 0 : tot1;
            for (int c = 0; c < 128; c++) {
                int v = hist[c * 64 + tid];
                hist[c * 64 + tid] = (unsigned short)run;
                run += v;
            }
            if (s == 0) tot1 = run;
            else g_cnt[g * 64 + tid] = run;
        }
        __syncthreads();

        const float* gsrc = (s == 0) ? g_gate1 : g_gate2;
#pragma unroll
        for (int jj = 0; jj < 4; jj++) {
            int c = warp * 4 + jj;
            int pr = (int)hist[c * 64 + myE[jj]] + myLr[jj];
            if (pr < Cd) {
                long long idx = (((long long)(g * Td + myT[jj]) * Ed + myE[jj]) * Cd + pr);
                float gate = gsrc[g * Td + myT[jj]];
                out[idx] = 1.0f;          // dispatch
                out[GTEC + idx] = gate;   // combine
            }
        }
        __syncthreads();
    }
}

// ---------------------------------------------------------------------------
// Kernel 3: finalize aux_loss and z_loss scalars.
// ---------------------------------------------------------------------------
__global__ void __launch_bounds__(64) k_final(float* __restrict__ out) {
    __shared__ float red[4];
    int tid = threadIdx.x;  // 64 threads
    float term = 0.f;
    for (int g = 0; g < Gd; g++) {
        float sp = 0.f;
        for (int bb = 0; bb < 64; bb++) sp += g_sumP_part[g * 64 + bb][tid];
        term += (float)g_cnt[g * 64 + tid] * sp;
    }
    float z = g_z_part[tid] + g_z_part[tid + 64] + g_z_part[tid + 128] + g_z_part[tid + 192];
#pragma unroll
    for (int o = 16; o; o >>= 1) {
        term += __shfl_xor_sync(0xffffffffu, term, o);
        z += __shfl_xor_sync(0xffffffffu, z, o);
    }
    if ((tid & 31) == 0) { red[tid >> 5] = term; red[2 + (tid >> 5)] = z; }
    __syncthreads();
    if (tid == 0) {
        float T2 = red[0] + red[1];
        float Z2 = red[2] + red[3];
        out[2 * GTEC]     = T2 * (64.0f / (4.0f * 4096.0f * 4096.0f));
        out[2 * GTEC + 1] = Z2 * (1.0f / (4.0f * 4096.0f * 64.0f));
    }
}

// ---------------------------------------------------------------------------
extern "C" void kernel_launch(void* const* d_in, const int* in_sizes, int n_in,
                              void* d_out, int out_size) {
    const float* X = (const float*)d_in[0];
    const float* W = (const float*)d_in[1];
    const float* b = (const float*)d_in[2];
    float* out = (float*)d_out;

    // Bulk zero of the sparse output via driver-optimized memset node.
    cudaMemsetAsync(d_out, 0, (size_t)out_size * sizeof(float), 0);

    k_gemm<<<NB_G, 256>>>(X, W, b);
    k_route<<<Gd, 1024>>>(out);
    k_final<<<1, 64>>>(out);
}

// round 8
// speedup vs baseline: 1.3700x; 1.3700x over previous
#include <cuda_runtime.h>
#include <math.h>

// Problem constants
namespace {
constexpr int Gd = 4, Td = 4096, Dd = 2048, Ed = 64, Cd = 128;
constexpr int GT = Gd * Td;                         // 16384 tokens
constexpr long long GTEC = (long long)GT * Ed * Cd; // 134217728
constexpr int NB_G = 128;                           // GEMM blocks (128 rows each)
constexpr int NB_Z = 768;                           // zero-only blocks
constexpr int NBTOT = NB_G + NB_Z;                  // 896
constexpr long long N4 = (2 * GTEC) / 4;            // 67108864 float4s to zero
constexpr long long CHUNK_Z = 76288;                // f4 per zero block (596/thread)
constexpr long long N_A = CHUNK_Z * NB_Z;           // 58589184
constexpr long long CHUNK_G = 66560;                // f4 per gemm block (520/thread)
// N_A + NB_G*CHUNK_G == N4 (58589184 + 8519680 = 67108864)
}

// Scratch (fully overwritten every launch -> deterministic)
__device__ float g_gate1[GT];
__device__ float g_gate2[GT];
__device__ int   g_idx[GT];                // idx1 | idx2<<8
__device__ float g_sumP_part[NB_G][Ed];    // per-block sum of probs per expert
__device__ float g_z_part[NB_G];           // per-block z-loss partial
__device__ int   g_cnt[Gd * Ed];           // tokens per (group, expert) in top-2

// ---------------------------------------------------------------------------
// Kernel 1 (fused): blocks [0,NB_G) do 128-row GEMM (8x8 register tile per
// thread) + softmax + top2 + loss partials + a small contiguous zero slice;
// blocks [NB_G,NBTOT) zero-fill contiguous chunks of region A.
// ---------------------------------------------------------------------------
__global__ void __launch_bounds__(128, 3) k_main(const float* __restrict__ X,
                                                  const float* __restrict__ W,
                                                  const float* __restrict__ bias_v,
                                                  float* __restrict__ out) {
    const int tid = threadIdx.x;
    const int bid = blockIdx.x;
    const float4 z4 = make_float4(0.f, 0.f, 0.f, 0.f);
    float4* o4 = (float4*)out;

    if (bid >= NB_G) {
        // ---------- zero-fill role: contiguous chunk of region A ----------
        long long base = (long long)(bid - NB_G) * CHUNK_Z + tid;
#pragma unroll 4
        for (int k = 0; k < (int)(CHUNK_Z / 128); k++)
            o4[base + (long long)k * 128] = z4;
        return;
    }

    // ---------- GEMM role: 128 rows x 64 cols, K=2048, 8x8/thread ----------
    __shared__ float smem_raw[128 * 65];   // 33.3KB: union(As 8KB + Bs 4KB | S)
    __shared__ float rowz[128];
    float (*As)[128] = (float(*)[128])smem_raw;            // [16][128]
    float (*Bs)[64]  = (float(*)[64])(smem_raw + 2048);    // [16][64]
    float (*S)[65]   = (float(*)[65])smem_raw;             // [128][65]

    const int m0 = bid * 128;
    const int tx = tid & 7;    // 8 in N dir -> 8 cols each
    const int ty = tid >> 3;   // 16 in M dir -> 8 rows each (4 row-pairs)

    unsigned long long acc2[4][8];
#pragma unroll
    for (int i = 0; i < 4; i++)
#pragma unroll
        for (int j = 0; j < 8; j++) acc2[i][j] = 0ull;

    // tile-load mapping
    const int rbase = tid >> 2, qA = tid & 3;   // X: 512 float4s, 4/thread
    const int kwb = tid >> 4, e4 = tid & 15;    // W: 256 float4s, 2/thread
    const float* Xb = X + (long long)m0 * Dd + qA * 4;
    const float* Wb = W + (long long)kwb * Ed + e4 * 4;

    float4 xa[4], wb[2];
#pragma unroll
    for (int p = 0; p < 4; p++)
        xa[p] = *(const float4*)(Xb + (long long)(p * 32 + rbase) * Dd);
    wb[0] = *(const float4*)(Wb);
    wb[1] = *(const float4*)(Wb + 8 * Ed);

#pragma unroll
    for (int p = 0; p < 4; p++) {
        int r = p * 32 + rbase;
        As[qA * 4 + 0][r] = xa[p].x; As[qA * 4 + 1][r] = xa[p].y;
        As[qA * 4 + 2][r] = xa[p].z; As[qA * 4 + 3][r] = xa[p].w;
    }
    *(float4*)&Bs[kwb][e4 * 4]     = wb[0];
    *(float4*)&Bs[kwb + 8][e4 * 4] = wb[1];
    __syncthreads();

    constexpr int NTILES = Dd / 16;   // 128
    for (int t = 0; t < NTILES; t++) {
        if (t + 1 < NTILES) {
            const float* Xo = Xb + (t + 1) * 16;
#pragma unroll
            for (int p = 0; p < 4; p++)
                xa[p] = *(const float4*)(Xo + (long long)(p * 32 + rbase) * Dd);
            const float* Wo = Wb + (long long)(t + 1) * 16 * Ed;
            wb[0] = *(const float4*)(Wo);
            wb[1] = *(const float4*)(Wo + 8 * Ed);
        }
#pragma unroll
        for (int kk = 0; kk < 16; kk++) {
            ulonglong2 aA = *(const ulonglong2*)&As[kk][ty * 8];
            ulonglong2 aB = *(const ulonglong2*)&As[kk][ty * 8 + 4];
            unsigned long long ap[4] = {aA.x, aA.y, aB.x, aB.y};
            float4 b0 = *(const float4*)&Bs[kk][tx * 8];
            float4 b1 = *(const float4*)&Bs[kk][tx * 8 + 4];
            unsigned long long bd[8];
            asm("mov.b64 %0, {%1,%1};" : "=l"(bd[0]) : "f"(b0.x));
            asm("mov.b64 %0, {%1,%1};" : "=l"(bd[1]) : "f"(b0.y));
            asm("mov.b64 %0, {%1,%1};" : "=l"(bd[2]) : "f"(b0.z));
            asm("mov.b64 %0, {%1,%1};" : "=l"(bd[3]) : "f"(b0.w));
            asm("mov.b64 %0, {%1,%1};" : "=l"(bd[4]) : "f"(b1.x));
            asm("mov.b64 %0, {%1,%1};" : "=l"(bd[5]) : "f"(b1.y));
            asm("mov.b64 %0, {%1,%1};" : "=l"(bd[6]) : "f"(b1.z));
            asm("mov.b64 %0, {%1,%1};" : "=l"(bd[7]) : "f"(b1.w));
#pragma unroll
            for (int i = 0; i < 4; i++)
#pragma unroll
                for (int j = 0; j < 8; j++)
                    asm("fma.rn.f32x2 %0, %1, %2, %0;"
                        : "+l"(acc2[i][j]) : "l"(ap[i]), "l"(bd[j]));
        }
        __syncthreads();
        if (t + 1 < NTILES) {
#pragma unroll
            for (int p = 0; p < 4; p++) {
                int r = p * 32 + rbase;
                As[qA * 4 + 0][r] = xa[p].x; As[qA * 4 + 1][r] = xa[p].y;
                As[qA * 4 + 2][r] = xa[p].z; As[qA * 4 + 3][r] = xa[p].w;
            }
            *(float4*)&Bs[kwb][e4 * 4]     = wb[0];
            *(float4*)&Bs[kwb + 8][e4 * 4] = wb[1];
            __syncthreads();
        }
    }

    // unpack accumulators (+bias) into S as logits (As/Bs dead now)
    float bcol[8];
    *(float4*)&bcol[0] = *(const float4*)&bias_v[tx * 8];
    *(float4*)&bcol[4] = *(const float4*)&bias_v[tx * 8 + 4];
#pragma unroll
    for (int i = 0; i < 4; i++) {
#pragma unroll
        for (int j = 0; j < 8; j++) {
            float lo, hi;
            asm("mov.b64 {%0,%1}, %2;" : "=f"(lo), "=f"(hi) : "l"(acc2[i][j]));
            S[ty * 8 + 2 * i + 0][tx * 8 + j] = lo + bcol[j];
            S[ty * 8 + 2 * i + 1][tx * 8 + j] = hi + bcol[j];
        }
    }
    __syncthreads();

    // per-row softmax / top-2 / z partial (128 rows, one thread per row)
    {
        const int r = tid;
        const int row = m0 + r;
        float mx = -3.0e38f;
#pragma unroll 8
        for (int e = 0; e < Ed; e++) mx = fmaxf(mx, S[r][e]);
        float sum = 0.f;
        float l1 = -3.0e38f, l2 = -3.0e38f;
        int i1 = 0, i2 = 0;
        for (int e = 0; e < Ed; e++) {
            float L = S[r][e];
            sum += expf(L - mx);
            if (L > l1) { l2 = l1; i2 = i1; l1 = L; i1 = e; }
            else if (L > l2) { l2 = L; i2 = e; }
        }
        float lse = mx + logf(sum);
        float zr = 0.f;
        for (int e = 0; e < Ed; e++) {
            float d = S[r][e] - lse;
            zr += d * d;
        }
        rowz[r] = zr;
        g_gate1[row] = expf(l1 - mx) / sum;
        g_gate2[row] = expf(l2 - mx) / sum;
        g_idx[row] = i1 | (i2 << 8);
        for (int e = 0; e < Ed; e++) S[r][e] = expf(S[r][e] - mx) / sum;
    }
    __syncthreads();

    // column sums of probs -> per-block partials for aux loss
    if (tid < 64) {
        float s = 0.f;
#pragma unroll 8
        for (int r = 0; r < 128; r++) s += S[r][tid];
        g_sumP_part[bid][tid] = s;
    }
    if (tid < 32) {
        float s = rowz[tid] + rowz[tid + 32] + rowz[tid + 64] + rowz[tid + 96];
#pragma unroll
        for (int o = 16; o; o >>= 1) s += __shfl_xor_sync(0xffffffffu, s, o);
        if (tid == 0) g_z_part[bid] = s;
    }

    // ---------- zero-fill role: contiguous slice of region B ----------
    {
        long long base = N_A + (long long)bid * CHUNK_G + tid;
#pragma unroll 4
        for (int k = 0; k < (int)(CHUNK_G / 128); k++)
            o4[base + (long long)k * 128] = z4;
    }
}

// ---------------------------------------------------------------------------
// Kernel 2: per-group BPR sort + capacity assignment + sparse scatter.
// One block per group, 1024 threads.
// ---------------------------------------------------------------------------
__global__ void __launch_bounds__(1024) k_route(float* __restrict__ out) {
    __shared__ unsigned long long keys[4096];  // 32KB (later reused as hist)
    __shared__ unsigned short tok[4096];       // 8KB

    const int tid = threadIdx.x;
    const int g = blockIdx.x;
    const int lane = tid & 31;
    const int warp = tid >> 5;                 // 0..31
    const unsigned lt = (1u << lane) - 1u;

    // keys: descending gate1, ties -> ascending token index (stable)
    for (int i = tid; i < Td; i += 1024) {
        unsigned u = __float_as_uint(g_gate1[g * Td + i]);
        unsigned o = (u >> 31) ? ~u : (u | 0x80000000u);
        keys[i] = (((unsigned long long)(~o)) << 32) | (unsigned)i;
    }
    __syncthreads();

    // bitonic sort ascending (4096 elements)
    for (unsigned k = 2; k <= 4096; k <<= 1) {
        for (unsigned j = k >> 1; j > 0; j >>= 1) {
            for (unsigned i = tid; i < 4096; i += 1024) {
                unsigned ixj = i ^ j;
                if (ixj > i) {
                    unsigned long long a = keys[i], b = keys[ixj];
                    bool up = ((i & k) == 0);
                    if ((a > b) == up) { keys[i] = b; keys[ixj] = a; }
                }
            }
            __syncthreads();
        }
    }

    for (int i = tid; i < Td; i += 1024) tok[i] = (unsigned short)(keys[i] & 0xffffu);
    __syncthreads();

    unsigned short* hist = (unsigned short*)keys;  // [128 chunks][64 experts]
    unsigned* h32 = (unsigned*)keys;

    int tot1 = 0;  // per-expert top-1 totals kept in registers of threads tid<64

    for (int s = 0; s < 2; s++) {
        for (int i = tid; i < 4096; i += 1024) h32[i] = 0u;
        __syncthreads();

        int myE[4], myLr[4], myT[4];
#pragma unroll
        for (int jj = 0; jj < 4; jj++) {
            int c = warp * 4 + jj;          // chunk of 32 sorted positions
            int p = c * 32 + lane;
            int t = tok[p];
            int packed = g_idx[g * Td + t];
            int e = (s == 0) ? (packed & 0xff) : ((packed >> 8) & 0xff);
            unsigned m = __match_any_sync(0xffffffffu, e);
            int lr = __popc(m & lt);
            if ((m & lt) == 0) hist[c * 64 + e] = (unsigned short)__popc(m);
            myE[jj] = e; myLr[jj] = lr; myT[jj] = t;
        }
        __syncthreads();

        // exclusive scan over chunks per expert
        if (tid < 64) {
            int run = (s == 0) ? 0 : tot1;
            for (int c = 0; c < 128; c++) {
                int v = hist[c * 64 + tid];
                hist[c * 64 + tid] = (unsigned short)run;
                run += v;
            }
            if (s == 0) tot1 = run;
            else g_cnt[g * 64 + tid] = run;
        }
        __syncthreads();

        const float* gsrc = (s == 0) ? g_gate1 : g_gate2;
#pragma unroll
        for (int jj = 0; jj < 4; jj++) {
            int c = warp * 4 + jj;
            int pr = (int)hist[c * 64 + myE[jj]] + myLr[jj];
            if (pr < Cd) {
                long long idx = (((long long)(g * Td + myT[jj]) * Ed + myE[jj]) * Cd + pr);
                float gate = gsrc[g * Td + myT[jj]];
                out[idx] = 1.0f;          // dispatch
                out[GTEC + idx] = gate;   // combine
            }
        }
        __syncthreads();
    }
}

// ---------------------------------------------------------------------------
// Kernel 3: finalize aux_loss and z_loss scalars.
// ---------------------------------------------------------------------------
__global__ void __launch_bounds__(64) k_final(float* __restrict__ out) {
    __shared__ float red[4];
    int tid = threadIdx.x;  // 64 threads
    float term = 0.f;
    for (int g = 0; g < Gd; g++) {
        float sp = 0.f;
        for (int bb = 0; bb < 32; bb++) sp += g_sumP_part[g * 32 + bb][tid];
        term += (float)g_cnt[g * 64 + tid] * sp;
    }
    float z = g_z_part[tid] + g_z_part[tid + 64];
#pragma unroll
    for (int o = 16; o; o >>= 1) {
        term += __shfl_xor_sync(0xffffffffu, term, o);
        z += __shfl_xor_sync(0xffffffffu, z, o);
    }
    if ((tid & 31) == 0) { red[tid >> 5] = term; red[2 + (tid >> 5)] = z; }
    __syncthreads();
    if (tid == 0) {
        float T2 = red[0] + red[1];
        float Z2 = red[2] + red[3];
        out[2 * GTEC]     = T2 * (64.0f / (4.0f * 4096.0f * 4096.0f));
        out[2 * GTEC + 1] = Z2 * (1.0f / (4.0f * 4096.0f * 64.0f));
    }
}

// ---------------------------------------------------------------------------
extern "C" void kernel_launch(void* const* d_in, const int* in_sizes, int n_in,
                              void* d_out, int out_size) {
    const float* X = (const float*)d_in[0];
    const float* W = (const float*)d_in[1];
    const float* b = (const float*)d_in[2];
    float* out = (float*)d_out;

    k_main<<<NBTOT, 128>>>(X, W, b, out);
    k_route<<<Gd, 1024>>>(out);
    k_final<<<1, 64>>>(out);
}